// round 11
// baseline (speedup 1.0000x reference)
#include <cuda_runtime.h>
#include <math.h>

#define N_MAX   65536
#define NF      64
#define LORD    5
#define RING    2048
#define RPAD    16
#define BLOCK   512          // 16 warps, 1 sample/thread
#define WCAP    512
#define M32N    (N_MAX / 32)
#define ZCLAMP  801          // COEFF_VEC_SIZE(807) - (L_ORDER+1)
#define IB_SAMP 1024
#define IB_THR  256

// ---------------- device scratch (no allocations allowed) ----------------
__device__ __align__(16) float4 g_vals4[N_MAX * 2];  // per sample: v0..v5, x, z_bits
__device__ __align__(16) float4 g_comp[N_MAX * 5];   // per sample: (X,Lmin,0,0), W0..15
__device__ int g_m32[M32N];                          // min Lmin per 32-sample block

__device__ __forceinline__ float tin_f(int i) {
    return (float)((double)i / 63.0);
}

// ---------------- kernel 1: fused prep + spline eval + taps ----------------
__global__ void __launch_bounds__(IB_THR)
interp_kernel(const float* __restrict__ delay, const float* __restrict__ raw,
              const float* __restrict__ exc, int burst, int n) {
    __shared__ float yf[6][NF];
    __shared__ float w[62];
    __shared__ float dpS[6][62];
    __shared__ float Ms[6][64];
    __shared__ float spy[6][64];
    __shared__ float spb[6][63];
    __shared__ float spc[6][63];
    __shared__ float spd[6][63];
    int tid = threadIdx.x;
    if (burst > n) burst = n;

    if (tid < NF) {
        float s[LORD]; float sum = 0.f;
        #pragma unroll
        for (int l = 0; l < LORD; l++) {
            s[l] = 1.0f / (1.0f + expf(-raw[tid * LORD + l]));
            sum += s[l];
        }
        #pragma unroll
        for (int l = 0; l < LORD; l++) yf[1 + l][tid] = s[l] / sum;
        yf[0][tid] = delay[tid];
    }
    if (tid == IB_THR - 1) {
        float wv = 0.25f; w[0] = wv;
        #pragma unroll
        for (int k = 1; k < 62; k++) { wv = 1.0f / (4.0f - wv); w[k] = wv; }
    }
    __syncthreads();

    if (tid < 6) {
        const float rs = 6.0f * 63.0f * 63.0f;
        float yim1 = yf[tid][0];
        float yi   = yf[tid][1];
        float prev = 0.f;
        #pragma unroll
        for (int k = 0; k < 62; k++) {
            float yip1 = yf[tid][k + 2];
            float r = rs * (yip1 - 2.0f * yi + yim1);
            prev = (k == 0) ? r * w[0] : (r - prev) * w[k];
            dpS[tid][k] = prev;
            yim1 = yi; yi = yip1;
        }
        Ms[tid][63] = 0.0f;
        Ms[tid][0]  = 0.0f;
        float mnext = dpS[tid][61];
        Ms[tid][62] = mnext;
        #pragma unroll
        for (int k = 60; k >= 0; k--) {
            mnext = dpS[tid][k] - w[k] * Ms[tid][k + 2];
            Ms[tid][k + 1] = mnext;
        }
        spy[tid][63] = yf[tid][63];
    }
    __syncthreads();

    for (int e = tid; e < 6 * 63; e += IB_THR) {
        int ch = e / 63, i = e - ch * 63;
        float y0 = yf[ch][i], y1 = yf[ch][i + 1];
        float M0 = Ms[ch][i], M1 = Ms[ch][i + 1];
        float b = (y1 - y0) * 63.0f - (1.0f / 63.0f) * (2.0f * M0 + M1) * (1.0f / 6.0f);
        spy[ch][i] = y0;
        spb[ch][i] = b;
        spc[ch][i] = M0 * 0.5f;
        spd[ch][i] = (M1 - M0) * (63.0f / 6.0f);
    }
    __syncthreads();

    const double inv_nm1 = 1.0 / (double)(n - 1);
    int j0 = blockIdx.x * IB_SAMP + tid * 4;

    #pragma unroll
    for (int q = 0; q < 4; q++) {
        int j = j0 + q;
        if (j >= n) break;
        double td = (double)j * inv_nm1;
        float tf = (float)td;
        int i0 = (int)(td * 63.0);
        if (i0 > 62) i0 = 62;
        if (i0 < 0)  i0 = 0;
        while (i0 < 62 && tin_f(i0 + 1) <= tf) i0++;
        while (i0 > 0 && tin_f(i0) > tf) i0--;
        float dt = tf - tin_f(i0);

        float ch[6];
        #pragma unroll
        for (int cc = 0; cc < 6; cc++) {
            ch[cc] = spy[cc][i0] + spb[cc][i0] * dt
                   + spc[cc][i0] * dt * dt + spd[cc][i0] * dt * dt * dt;
        }

        float dl = ch[0];
        float zf = floorf(dl);
        int   z  = (int)zf;
        float alfa = dl - zf;
        float om = 1.0f - alfa;
        float b0 = ch[1], b1 = ch[2], b2 = ch[3], b3 = ch[4], b4 = ch[5];

        int zc = z; if (zc < 0) zc = 0; if (zc > ZCLAMP) zc = ZCLAMP;
        float x = (j < burst) ? exc[j] : 0.0f;

        float4 vA = make_float4(-om * b0,
                                -(alfa * b0 + om * b1),
                                -(alfa * b1 + om * b2),
                                -(alfa * b2 + om * b3));
        float4 vB = make_float4(-(alfa * b3 + om * b4),
                                -alfa * b4,
                                x,
                                __int_as_float(zc));
        g_vals4[(size_t)j * 2]     = vA;
        g_vals4[(size_t)j * 2 + 1] = vB;
    }
}

// ---------------- kernel 2: one-step composition (2x dependency distance) ----
// y[t] = X[t] + sum_{j,k} v[t,j]*v[s_j,k] * y[s_j-1-z_{s_j}-k],  s_j = t-1-z_t-j
// X[t] = x[t] - sum_j v[t,j]*x[s_j]. Lags are contiguous within 16 slots.
__global__ void __launch_bounds__(256)
compose_kernel(int n) {
    int t = blockIdx.x * 256 + threadIdx.x;
    int Lmin = 0x3fffffff;
    if (t < n) {
        float4 A = g_vals4[(size_t)t * 2];
        float4 B = g_vals4[(size_t)t * 2 + 1];
        float v[6] = {A.x, A.y, A.z, A.w, B.x, B.y};
        int zt = __float_as_int(B.w);
        float X = B.z;
        float W[16];
        #pragma unroll
        for (int m = 0; m < 16; m++) W[m] = 0.f;

        float4 Aj[6], Bj[6];
        int lag0[6];
        bool val[6];
        int s0 = t - 1 - zt;
        #pragma unroll
        for (int j = 0; j < 6; j++) {
            int sj = s0 - j;
            val[j] = (sj >= 0);
            lag0[j] = 0;
            if (val[j]) {
                Aj[j] = g_vals4[(size_t)sj * 2];
                Bj[j] = g_vals4[(size_t)sj * 2 + 1];
                int zs = __float_as_int(Bj[j].w);
                lag0[j] = 2 + zt + j + zs;
                if (lag0[j] < Lmin) Lmin = lag0[j];
                X -= v[j] * Bj[j].z;     // x[s_j] contribution
            }
        }
        bool any = (Lmin != 0x3fffffff);
        #pragma unroll
        for (int j = 0; j < 6; j++) {
            if (val[j]) {
                float vj[6] = {Aj[j].x, Aj[j].y, Aj[j].z, Aj[j].w, Bj[j].x, Bj[j].y};
                int bm = lag0[j] - Lmin;
                #pragma unroll
                for (int k = 0; k < 6; k++) {
                    int m = bm + k;
                    if ((unsigned)m < 16u) W[m] += v[j] * vj[k];
                }
            }
        }
        if (!any) Lmin = 1 << 20;   // no taps: zero coeffs, masked reads harmless
        g_comp[(size_t)t * 5]     = make_float4(X, __int_as_float(Lmin), 0.f, 0.f);
        g_comp[(size_t)t * 5 + 1] = make_float4(W[0],  W[1],  W[2],  W[3]);
        g_comp[(size_t)t * 5 + 2] = make_float4(W[4],  W[5],  W[6],  W[7]);
        g_comp[(size_t)t * 5 + 3] = make_float4(W[8],  W[9],  W[10], W[11]);
        g_comp[(size_t)t * 5 + 4] = make_float4(W[12], W[13], W[14], W[15]);
    }
    // per-32-sample min of Lmin (warp-aligned; one write per warp)
    int lm = Lmin;
    #pragma unroll
    for (int off = 16; off; off >>= 1) {
        int o = __shfl_xor_sync(0xffffffffu, lm, off);
        if (o < lm) lm = o;
    }
    if ((threadIdx.x & 31) == 0) {
        int mi = t >> 5;
        if (mi < M32N) g_m32[mi] = lm;
    }
}

// ---------------- kernel 3: chunked IIR on composed taps ----------------
__global__ void __launch_bounds__(BLOCK, 1)
iir_kernel(float* __restrict__ out, int n) {
    __shared__ __align__(16) float ringraw[RING + RPAD]; // [0..15] mirror of 2032..2047
    __shared__ int sm32[M32N];
    __shared__ int swb[M32N];
    int tid = threadIdx.x;
    const float4* __restrict__ comp = g_comp;
    float* ringp = ringraw + RPAD;

    for (int i = tid; i < RING + RPAD; i += BLOCK) ringraw[i] = 0.0f;
    for (int i = tid; i < M32N; i += BLOCK) sm32[i] = g_m32[i];
    __syncthreads();

    // Wb[i] = min(Lmin over blocks i..i+16), cap WCAP.
    // start <= 32i+31, last sample <= 32i+31+511 < 32(i+17)
    for (int i = tid; i < M32N; i += BLOCK) {
        int v = 0x3fffffff;
        #pragma unroll
        for (int k = 0; k < 17; k++) {
            int idx = i + k;
            if (idx < M32N) { int m = sm32[idx]; if (m < v) v = m; }
        }
        int Wv = v;                 // need W <= Lmin (taps strictly older than chunk)
        if (Wv > WCAP) Wv = WCAP;
        if (Wv < 1)    Wv = 1;
        swb[i] = Wv;
    }
    __syncthreads();

    #define WB_AT(pos) swb[((pos) >> 5) < (M32N - 1) ? ((pos) >> 5) : (M32N - 1)]
    int W0 = WB_AT(0);
    int c1 = W0;       int W1 = WB_AT(c1);
    int c2 = c1 + W1;  int W2 = WB_AT(c2);
    int c3 = c2 + W2;  int W3 = WB_AT(c3);
    int s4 = c3 + W3;  int W4 = WB_AT(s4);

    float4 z4 = make_float4(0,0,0,0);
    float4 H0=z4,D00=z4,D01=z4,D02=z4,D03=z4;
    float4 H1=z4,D10=z4,D11=z4,D12=z4,D13=z4;
    float4 H2=z4,D20=z4,D21=z4,D22=z4,D23=z4;
    float4 H3=z4,D30=z4,D31=z4,D32=z4,D33=z4;

    #define LOADST(H_,Da_,Db_,Dc_,Dd_, cs, Ws)                                  \
    {   int tS = (cs) + tid;                                                    \
        if (tid < (Ws) && tS < n) {                                             \
            const float4* pc = &comp[(size_t)tS * 5];                           \
            H_ = pc[0]; Da_ = pc[1]; Db_ = pc[2]; Dc_ = pc[3]; Dd_ = pc[4];     \
        } }

    LOADST(H0,D00,D01,D02,D03, 0,  W0);
    LOADST(H1,D10,D11,D12,D13, c1, W1);
    LOADST(H2,D20,D21,D22,D23, c2, W2);
    LOADST(H3,D30,D31,D32,D33, c3, W3);

    // precompute chunk 0: predicate, tap base, store slot
    bool p  = (tid < W0) && (tid < n);
    int  ai = (tid - __float_as_int(H0.y)) & (RING - 1);
    int  ns = tid & (RING - 1);

    int c = 0;
    int next_dump = 1024;

    #define ITER(Hx,Da,Db,Dc,Dd, HyN)                                           \
    {                                                                           \
        int s5 = s4 + W4;                                                       \
        int W5 = WB_AT(s5);                                                     \
        if (c >= next_dump) {                                                   \
            if (tid < 256) {                                                    \
                int i4 = (next_dump - 1024) + (tid << 2);                       \
                float4 vq = *(const float4*)&ringp[i4 & (RING - 1)];            \
                *(float4*)&out[i4] = vq;                                        \
            }                                                                   \
            next_dump += 1024;                                                  \
        }                                                                       \
        if (p) {                                                                \
            float r0  = ringp[ai],      r1  = ringp[ai - 1];                    \
            float r2  = ringp[ai - 2],  r3  = ringp[ai - 3];                    \
            float r4  = ringp[ai - 4],  r5  = ringp[ai - 5];                    \
            float r6  = ringp[ai - 6],  r7  = ringp[ai - 7];                    \
            float r8  = ringp[ai - 8],  r9  = ringp[ai - 9];                    \
            float r10 = ringp[ai - 10], r11 = ringp[ai - 11];                   \
            float r12 = ringp[ai - 12], r13 = ringp[ai - 13];                   \
            float r14 = ringp[ai - 14], r15 = ringp[ai - 15];                   \
            float q0 = Da.x * r0  + Da.y * r1  + Da.z * r2  + Da.w * r3;        \
            float q1 = Db.x * r4  + Db.y * r5  + Db.z * r6  + Db.w * r7;        \
            float q2 = Dc.x * r8  + Dc.y * r9  + Dc.z * r10 + Dc.w * r11;       \
            float q3 = Dd.x * r12 + Dd.y * r13 + Dd.z * r14 + Dd.w * r15;       \
            float acc = Hx.x + (q0 + q1) + (q2 + q3);                           \
            ringp[ns] = acc;                                                    \
            if (ns >= RING - 15) ringp[ns - RING] = acc;  /* maintain mirror */ \
        }                                                                       \
        LOADST(Hx,Da,Db,Dc,Dd, s4, W4);       /* refill for chunk k+4 */        \
        {   int cn = c + W0;                                                    \
            int t1 = cn + tid;                                                  \
            p  = (tid < W1) && (t1 < n);                                        \
            ai = (t1 - __float_as_int(HyN.y)) & (RING - 1);                     \
            ns = t1 & (RING - 1);                                               \
            c  = cn; }                                                          \
        __syncthreads();                      /* single barrier per chunk */    \
        W0 = W1; W1 = W2; W2 = W3; W3 = W4; W4 = W5; s4 = s5;                   \
    }

    while (c < n) {
        ITER(H0,D00,D01,D02,D03, H1);
        if (c >= n) break;
        ITER(H1,D10,D11,D12,D13, H2);
        if (c >= n) break;
        ITER(H2,D20,D21,D22,D23, H3);
        if (c >= n) break;
        ITER(H3,D30,D31,D32,D33, H0);
    }
    #undef ITER
    #undef LOADST
    #undef WB_AT

    __syncthreads();
    for (int i = (next_dump - 1024) + tid; i < n; i += BLOCK)
        out[i] = ringp[i & (RING - 1)];
}

// ---------------- launch ----------------
extern "C" void kernel_launch(void* const* d_in, const int* in_sizes, int n_in,
                              void* d_out, int out_size) {
    const float* delay = (const float*)d_in[0];
    const float* raw   = (const float*)d_in[1];
    const float* exc   = (const float*)d_in[2];
    int burst = in_sizes[2];
    int n = out_size;
    if (n > N_MAX) n = N_MAX;

    int iblocks = (n + IB_SAMP - 1) / IB_SAMP;
    interp_kernel<<<iblocks, IB_THR>>>(delay, raw, exc, burst, n);
    compose_kernel<<<(n + 255) / 256, 256>>>(n);
    iir_kernel<<<1, BLOCK>>>((float*)d_out, n);
}

// round 12
// speedup vs baseline: 1.2984x; 1.2984x over previous
#include <cuda_runtime.h>
#include <math.h>

#define N_MAX   65536
#define NF      64
#define LORD    5
#define RING    2048
#define BLOCK   512          // 16 warps
#define WCAP    512
#define M32N    (N_MAX / 32)
#define ZCLAMP  801          // COEFF_VEC_SIZE(807) - (L_ORDER+1)
#define IB_SAMP 1024         // samples per interp block
#define IB_THR  256
#define W_INF   0.26794919243112270647f   // 2 - sqrt(3), fixed point of 1/(4-x)

// ---------------- device scratch (no allocations allowed) ----------------
__device__ __align__(16) float4 g_vals4[N_MAX * 2];  // per sample: v0..v5, x, z_bits
__device__ int g_m32[M32N];                          // min clamped z per 32-sample block

__device__ __forceinline__ float tin_f(int i) {
    // fp32 knot position, matching jnp.linspace(0,1,64)[i] to ~1 ulp
    return (float)((double)i / 63.0);
}

// ---------------- kernel 1: fused prep (per-block) + spline eval + taps ----------------
__global__ void __launch_bounds__(IB_THR)
interp_kernel(const float* __restrict__ delay, const float* __restrict__ raw,
              const float* __restrict__ exc, int burst, int n) {
    __shared__ float yf[6][NF];
    __shared__ float w[62];
    __shared__ float dpS[6][62];
    __shared__ float Ms[6][64];
    __shared__ float spy[6][64];
    __shared__ float spb[6][63];
    __shared__ float spc[6][63];
    __shared__ float spd[6][63];
    int tid = threadIdx.x;
    if (burst > n) burst = n;

    // --- phase 1: sigmoid coeffs (threads 0..63) + Thomas w table (one spare thread)
    if (tid < NF) {
        float s[LORD]; float sum = 0.f;
        #pragma unroll
        for (int l = 0; l < LORD; l++) {
            s[l] = 1.0f / (1.0f + expf(-raw[tid * LORD + l]));
            sum += s[l];
        }
        #pragma unroll
        for (int l = 0; l < LORD; l++) yf[1 + l][tid] = s[l] / sum;
        yf[0][tid] = delay[tid];
    }
    if (tid == IB_THR - 1) {
        // w[k] = 1/(4 - w[k-1]) contracts at ~0.072/step: converged to fp32
        // exactness well before k=20. Serial part 62 -> 20 divisions; the rest
        // is the fixed point 2 - sqrt(3) (same solve to fp32 rounding).
        float wv = 0.25f; w[0] = wv;
        #pragma unroll
        for (int k = 1; k < 20; k++) { wv = 1.0f / (4.0f - wv); w[k] = wv; }
        #pragma unroll
        for (int k = 20; k < 62; k++) w[k] = W_INF;
    }
    __syncthreads();

    // --- phase 2: Thomas forward/backward (6 threads, scratch in shared)
    if (tid < 6) {
        const float rs = 6.0f * 63.0f * 63.0f;   // 6/h^2
        float yim1 = yf[tid][0];
        float yi   = yf[tid][1];
        float prev = 0.f;
        #pragma unroll
        for (int k = 0; k < 62; k++) {
            float yip1 = yf[tid][k + 2];
            float r = rs * (yip1 - 2.0f * yi + yim1);
            prev = (k == 0) ? r * w[0] : (r - prev) * w[k];
            dpS[tid][k] = prev;
            yim1 = yi; yi = yip1;
        }
        Ms[tid][63] = 0.0f;
        Ms[tid][0]  = 0.0f;
        float mnext = dpS[tid][61];
        Ms[tid][62] = mnext;
        #pragma unroll
        for (int k = 60; k >= 0; k--) {
            mnext = dpS[tid][k] - w[k] * Ms[tid][k + 2];
            Ms[tid][k + 1] = mnext;
        }
        spy[tid][63] = yf[tid][63];
    }
    __syncthreads();

    // --- phase 3: emit interval coefficients (parallel over 6*63)
    for (int e = tid; e < 6 * 63; e += IB_THR) {
        int ch = e / 63, i = e - ch * 63;
        float y0 = yf[ch][i], y1 = yf[ch][i + 1];
        float M0 = Ms[ch][i], M1 = Ms[ch][i + 1];
        float b = (y1 - y0) * 63.0f - (1.0f / 63.0f) * (2.0f * M0 + M1) * (1.0f / 6.0f);
        spy[ch][i] = y0;
        spb[ch][i] = b;
        spc[ch][i] = M0 * 0.5f;
        spd[ch][i] = (M1 - M0) * (63.0f / 6.0f);
    }
    __syncthreads();

    // --- phase 4: evaluate 4 consecutive samples per thread
    const double inv_nm1 = 1.0 / (double)(n - 1);
    int j0 = blockIdx.x * IB_SAMP + tid * 4;
    int zmin = 0x7fffffff;

    #pragma unroll
    for (int q = 0; q < 4; q++) {
        int j = j0 + q;
        if (j >= n) break;
        double td = (double)j * inv_nm1;
        float tf = (float)td;
        int i0 = (int)(td * 63.0);
        if (i0 > 62) i0 = 62;
        if (i0 < 0)  i0 = 0;
        // replicate searchsorted(t_in, t_out, 'right')-1 in fp32 exactly
        while (i0 < 62 && tin_f(i0 + 1) <= tf) i0++;
        while (i0 > 0 && tin_f(i0) > tf) i0--;
        float dt = tf - tin_f(i0);

        float ch[6];
        #pragma unroll
        for (int cc = 0; cc < 6; cc++) {
            ch[cc] = spy[cc][i0] + spb[cc][i0] * dt
                   + spc[cc][i0] * dt * dt + spd[cc][i0] * dt * dt * dt;
        }

        float dl = ch[0];
        float zf = floorf(dl);
        int   z  = (int)zf;
        float alfa = dl - zf;
        float om = 1.0f - alfa;
        float b0 = ch[1], b1 = ch[2], b2 = ch[3], b3 = ch[4], b4 = ch[5];

        int zc = z; if (zc < 0) zc = 0; if (zc > ZCLAMP) zc = ZCLAMP;
        float x = (j < burst) ? exc[j] : 0.0f;

        float4 vA = make_float4(-om * b0,
                                -(alfa * b0 + om * b1),
                                -(alfa * b1 + om * b2),
                                -(alfa * b2 + om * b3));
        float4 vB = make_float4(-(alfa * b3 + om * b4),
                                -alfa * b4,
                                x,
                                __int_as_float(zc));
        g_vals4[(size_t)j * 2]     = vA;
        g_vals4[(size_t)j * 2 + 1] = vB;
        if (zc < zmin) zmin = zc;
    }

    // min over 8 consecutive lanes = one 32-sample block; no atomics needed
    #pragma unroll
    for (int off = 4; off; off >>= 1) {
        int o = __shfl_xor_sync(0xffffffffu, zmin, off);
        if (o < zmin) zmin = o;
    }
    if ((tid & 7) == 0) {
        int mi = j0 >> 5;
        if (mi < M32N) g_m32[mi] = zmin;
    }
}

// ---------------- kernel 2: chunked IIR, depth-4, addresses precomputed ----------------
__global__ void __launch_bounds__(BLOCK, 1)
iir_kernel(float* __restrict__ out, int n) {
    __shared__ float ring[RING];
    __shared__ int   sm32[M32N];
    __shared__ int   swb[M32N];   // chunk width if a chunk starts in this 32-block
    int tid = threadIdx.x;
    const float4* __restrict__ vals = g_vals4;

    for (int i = tid; i < RING; i += BLOCK) ring[i] = 0.0f;
    for (int i = tid; i < M32N; i += BLOCK) sm32[i] = g_m32[i];
    __syncthreads();

    // Wb[i] = min(m32[i .. i+17]) + 1, cap WCAP (512).
    for (int i = tid; i < M32N; i += BLOCK) {
        int v = 0x7fffffff;
        #pragma unroll
        for (int k = 0; k < 18; k++) {
            int idx = i + k;
            if (idx < M32N) { int m = sm32[idx]; if (m < v) v = m; }
        }
        int Wv = v + 1;
        if (Wv > WCAP) Wv = WCAP;
        if (Wv < 1)    Wv = 1;
        swb[i] = Wv;
    }
    __syncthreads();

    // ---- schedule prologue: chunks 0..4, buffers for chunks 0..3 ----
    #define WB_AT(pos) swb[((pos) >> 5) < (M32N - 1) ? ((pos) >> 5) : (M32N - 1)]
    int W0 = WB_AT(0);
    int c1 = W0;       int W1 = WB_AT(c1);
    int c2 = c1 + W1;  int W2 = WB_AT(c2);
    int c3 = c2 + W2;  int W3 = WB_AT(c3);
    int s4 = c3 + W3;  int W4 = WB_AT(s4);

    float4 A0 = make_float4(0,0,0,0), B0 = A0;
    float4 A1 = A0, B1 = A0, A2 = A0, B2 = A0, A3 = A0, B3 = A0;
    if (tid < W0 && tid < n) { A0 = vals[(size_t)tid * 2]; B0 = vals[(size_t)tid * 2 + 1]; }
    { int t = c1 + tid; if (tid < W1 && t < n) { A1 = vals[(size_t)t * 2]; B1 = vals[(size_t)t * 2 + 1]; } }
    { int t = c2 + tid; if (tid < W2 && t < n) { A2 = vals[(size_t)t * 2]; B2 = vals[(size_t)t * 2 + 1]; } }
    { int t = c3 + tid; if (tid < W3 && t < n) { A3 = vals[(size_t)t * 2]; B3 = vals[(size_t)t * 2 + 1]; } }

    // precompute chunk 0: predicate, LDS addresses, store index
    int  nt = tid;
    bool np = (tid < W0) && (tid < n);
    int  nb = tid - 1 - __float_as_int(B0.w);
    int na0 = (nb    ) & (RING - 1);
    int na1 = (nb - 1) & (RING - 1);
    int na2 = (nb - 2) & (RING - 1);
    int na3 = (nb - 3) & (RING - 1);
    int na4 = (nb - 4) & (RING - 1);
    int na5 = (nb - 5) & (RING - 1);

    int c = 0;

    // one chunk: body uses precomputed addrs; refill buffer for chunk k+4;
    // precompute addrs for chunk k+1 from the NEXT buffer's z (3 chunks of slack)
    #define ITER(Ax, Bx, Ay, By)                                                \
    {                                                                           \
        int s5 = s4 + W4;                                                       \
        int W5 = WB_AT(s5);                                                     \
        /* body: post-barrier chain is just LDS -> FFMA -> STS/STG */           \
        if (np) {                                                               \
            float r0 = ring[na0];                                               \
            float r1 = ring[na1];                                               \
            float r2 = ring[na2];                                               \
            float r3 = ring[na3];                                               \
            float r4 = ring[na4];                                               \
            float r5 = ring[na5];                                               \
            float p0 = Ax.x * r0 + Ax.z * r2 + Bx.x * r4;                       \
            float p1 = Ax.y * r1 + Ax.w * r3 + Bx.y * r5;                       \
            float acc = Bx.z - p0 - p1;                                         \
            ring[nt & (RING - 1)] = acc;                                        \
            out[nt] = acc;                                                      \
        }                                                                       \
        /* refill chunk k+4 into this buffer (in place, zero moves) */          \
        { int tp = s4 + tid;                                                    \
          if (tid < W4 && tp < n) {                                             \
              Ax = vals[(size_t)tp * 2];                                        \
              Bx = vals[(size_t)tp * 2 + 1];                                    \
          } }                                                                   \
        /* precompute chunk k+1 (buffer Ay/By already resident) */              \
        { int cn = c + W0;                                                      \
          int t1 = cn + tid;                                                    \
          np = (tid < W1) && (t1 < n);                                          \
          int b1_ = t1 - 1 - __float_as_int(By.w);                              \
          na0 = (b1_    ) & (RING - 1);                                         \
          na1 = (b1_ - 1) & (RING - 1);                                         \
          na2 = (b1_ - 2) & (RING - 1);                                         \
          na3 = (b1_ - 3) & (RING - 1);                                         \
          na4 = (b1_ - 4) & (RING - 1);                                         \
          na5 = (b1_ - 5) & (RING - 1);                                         \
          nt  = t1;                                                             \
          c   = cn; }                                                           \
        __syncthreads();   /* single barrier per chunk */                       \
        W0 = W1; W1 = W2; W2 = W3; W3 = W4; W4 = W5; s4 = s5;                   \
    }

    while (c < n) {
        ITER(A0, B0, A1, B1);
        if (c >= n) break;
        ITER(A1, B1, A2, B2);
        if (c >= n) break;
        ITER(A2, B2, A3, B3);
        if (c >= n) break;
        ITER(A3, B3, A0, B0);
    }
    #undef ITER
    #undef WB_AT
}

// ---------------- launch ----------------
extern "C" void kernel_launch(void* const* d_in, const int* in_sizes, int n_in,
                              void* d_out, int out_size) {
    const float* delay = (const float*)d_in[0];
    const float* raw   = (const float*)d_in[1];
    const float* exc   = (const float*)d_in[2];
    int burst = in_sizes[2];
    int n = out_size;
    if (n > N_MAX) n = N_MAX;

    int iblocks = (n + IB_SAMP - 1) / IB_SAMP;
    interp_kernel<<<iblocks, IB_THR>>>(delay, raw, exc, burst, n);
    iir_kernel<<<1, BLOCK>>>((float*)d_out, n);
}